// round 16
// baseline (speedup 1.0000x reference)
#include <cuda_runtime.h>
#include <math.h>

// SoftSkeletonLoss reduces analytically:
//  - soft_skeletonize(sigmoid-range input) == 0 after iteration 1 (conv3x3x3 of a
//    strictly positive field is > 0 -> eroded = opened = 1 -> skeleton = clip(x-1,0,1)=0),
//    so skeleton_loss = 1 - EPS/EPS = 0 exactly.
//  - Remaining: connectivity_loss = |comp_p - comp_t| where
//      comp = cnt / mean_nb,  mean_nb = (sum_masked(conv3x3x3(field)) + EPS*cnt) / max(cnt,1)
//    pred:   field = (pred > 0) binarized (sigmoid(x)>0.5 <=> x>0), mask = pred>0
//    target: field = target raw,                                     mask = target>0
//
// Fused 27-point box-sum reduction, tuned for OCCUPANCY: 256 threads,
// __launch_bounds__(256,5) -> <=51 regs -> 5 CTAs/SM (40 warps resident),
// 768 blocks (~5.2/SM). One z-plane per barrier with pure-issue one-ahead
// prefetch, x-halo via warp shuffles at consume time, separable x-presums in
// smem, psum middle row from own registers (2 LDS/plane), 4-bit center masks,
// predicated accumulate, last-block finalize with replay-safe reset.

#define DIMV   192
#define PLANE  (DIMV * DIMV)
#define TX     32
#define TY     24
#define CHUNK  48
#define HR     26              // halo rows (TY + 2)
#define SP     (HR * 32)       // one xs plane
#define NTHR   256
#define NBLK   (6 * 8 * 16)    // 768 blocks

// cnt_p, sum_p, cnt_t, sum_t (zero at module load; reset by last block each replay)
__device__ double   g_acc[4];
__device__ unsigned g_ticket;

__global__ __launch_bounds__(NTHR, 5)
void fused_skel_kernel(const float* __restrict__ pred,
                       const float* __restrict__ target,
                       float* __restrict__ out, int out_size) {
    __shared__ float sxs[2][SP];   // [buf][row*32+col] — double-buffered xs planes
    __shared__ float red[8][2];

    const int tid = threadIdx.x;
    const int bx0 = blockIdx.x * TX;
    const int by0 = blockIdx.y * TY;

    const int  zc     = blockIdx.z;            // 0..15
    const bool isPred = (zc < 8);
    const int  s      = zc & 7;                // 0..7
    const int  n      = s >> 2;                // sample 0..1
    const int  z0     = (s & 3) * CHUNK;

    const float* __restrict__ src =
        (isPred ? pred : target) + (size_t)n * ((size_t)DIMV * PLANE);

    // ---- loader identity: tid<208 loads halo row ly = tid>>3, chunk jj ----
    const int  ly    = tid >> 3;               // 0..31 (rows 0..25 active)
    const int  jj    = tid & 7;
    const bool lact  = (tid < 8 * HR);         // 208 loader threads
    const int  gy    = by0 + ly - 1;
    const bool rowIn = lact && ((unsigned)gy < (unsigned)DIMV);
    const bool ldE   = ((jj == 0) && (bx0 > 0)) || ((jj == 7) && (bx0 + TX < DIMV));
    const int  eOff  = (jj == 0) ? -1 : 4;
    const int  xsOff = ly * 32 + 4 * jj;

    int zf = z0 - 1;   // plane index of next fetch
    const float* lp = src + (long long)zf * PLANE + gy * DIMV + (bx0 + 4 * jj);

    float4 v;          // raw chunk of the most recently fetched plane
    float  e;          // boundary edge scalar

    // PURE-ISSUE fetch of plane zf (nothing consumes the results here)
    auto fetch = [&]() {
        const bool a = rowIn && ((unsigned)zf < (unsigned)DIMV);
        v = make_float4(0.f, 0.f, 0.f, 0.f); e = 0.f;
        if (a) { v = *(const float4*)lp; if (ldE) e = lp[eOff]; }
        lp += PLANE; ++zf;
    };

    // consume-time: x-halo shuffles + binarize (pred) + store 3-wide x-sums.
    // RETURNS the xs (kept in registers: it is the psum middle row).
    auto store_xs = [&](float* dst) -> float4 {
        float up = __shfl_up_sync(0xffffffffu, v.w, 1);   // col gx0-1
        float dn = __shfl_down_sync(0xffffffffu, v.x, 1); // col gx0+4
        float el = (jj == 0) ? e : up;
        float er = (jj == 7) ? e : dn;
        float a0, a1, a2, a3, b0, b1;
        if (isPred) {
            a0 = v.x > 0.f ? 1.f : 0.f; a1 = v.y > 0.f ? 1.f : 0.f;
            a2 = v.z > 0.f ? 1.f : 0.f; a3 = v.w > 0.f ? 1.f : 0.f;
            b0 = el  > 0.f ? 1.f : 0.f; b1 = er  > 0.f ? 1.f : 0.f;
        } else { a0 = v.x; a1 = v.y; a2 = v.z; a3 = v.w; b0 = el; b1 = er; }
        float t01 = a0 + a1, t12 = a1 + a2, t23 = a2 + a3;
        float4 xs = make_float4(b0 + t01, t01 + a2, t12 + a3, t23 + b1);
        if (lact) *(float4*)(dst + xsOff) = xs;
        return xs;
    };

    // ---- compute identity: tid in [8, 200) -> voxel row ty = ly-1 (0..23) ----
    const bool cact = (tid >= 8) && (tid < 8 + 8 * TY);
    // psum rows are xsOff-32 / xsOff+32; clamp for non-compute threads so the
    // LDS is always in-bounds (their contributions are nulled via mask = 0).
    const int  po   = cact ? xsOff : 64;

    // 4-bit center mask of this thread's 4 voxels (its own loaded chunk)
    auto mask4 = [&](const float4& c) -> int {
        if (!cact) return 0;
        return (c.x > 0.f ? 1 : 0) | (c.y > 0.f ? 2 : 0) |
               (c.z > 0.f ? 4 : 0) | (c.w > 0.f ? 8 : 0);
    };

    // psum: up/down rows from smem, middle row from the thread's own xs regs
    auto psum = [&](const float* sp, const float4& mid) -> float4 {
        float4 a = *(const float4*)(sp + po - 32);
        float4 c = *(const float4*)(sp + po + 32);
        return make_float4(a.x + mid.x + c.x, a.y + mid.y + c.y,
                           a.z + mid.z + c.z, a.w + mid.w + c.w);
    };

    // ---- prologue: plane z0-1 -> buf0, plane z0 -> buf1, prefetch z0+1 ----
    fetch();                                  // z0-1
    float4 xsA = store_xs(sxs[0]);
    fetch();                                  // z0
    __syncthreads();
    float4 pPrev = psum(sxs[0], xsA);         // P(z0-1)
    int    mCur  = mask4(v);                  // centers of plane z0
    float4 xsB   = store_xs(sxs[1]);
    fetch();                                  // z0+1
    __syncthreads();
    float4 pCur = psum(sxs[1], xsB);          // P(z0)

    float cnt = 0.f, sum = 0.f;

    // ---- main sweep: one barrier per plane; v holds plane z+1 on entry ----
    #pragma unroll 2
    for (int z = z0; z < z0 + CHUNK; ++z) {
        const int b = (z - z0) & 1;           // destination buffer for plane z+1
        const int mNext = mask4(v);           // centers of plane z+1
        float4 xsN = store_xs(sxs[b]);        // xs of plane z+1
        fetch();                              // pure-issue prefetch of plane z+2
        __syncthreads();
        float4 pNext = psum(sxs[b], xsN);     // P(z+1)

        if (mCur & 1) { cnt += 1.f; sum += pPrev.x + pCur.x + pNext.x; }
        if (mCur & 2) { cnt += 1.f; sum += pPrev.y + pCur.y + pNext.y; }
        if (mCur & 4) { cnt += 1.f; sum += pPrev.z + pCur.z + pNext.z; }
        if (mCur & 8) { cnt += 1.f; sum += pPrev.w + pCur.w + pNext.w; }

        pPrev = pCur; pCur = pNext; mCur = mNext;
    }

    // ---- block reduction (8 warps) ----
    #pragma unroll
    for (int o = 16; o; o >>= 1) {
        cnt += __shfl_down_sync(0xffffffffu, cnt, o);
        sum += __shfl_down_sync(0xffffffffu, sum, o);
    }
    const int wid  = tid >> 5;
    const int lane = tid & 31;
    if (lane == 0) { red[wid][0] = cnt; red[wid][1] = sum; }
    __syncthreads();

    if (tid == 0) {
        float c2 = 0.f, s2 = 0.f;
        #pragma unroll
        for (int w = 0; w < 8; ++w) { c2 += red[w][0]; s2 += red[w][1]; }
        const int ai = isPred ? 0 : 2;
        atomicAdd(&g_acc[ai],     (double)c2);
        atomicAdd(&g_acc[ai + 1], (double)s2);
        __threadfence();
        unsigned t = atomicAdd(&g_ticket, 1u);
        if (t == NBLK - 1) {
            // last block: finalize, write output, reset for next graph replay
            __threadfence();
            double cp = atomicAdd(&g_acc[0], 0.0);
            double sp = atomicAdd(&g_acc[1], 0.0);
            double ct = atomicAdd(&g_acc[2], 0.0);
            double st = atomicAdd(&g_acc[3], 0.0);
            const double eps = 1e-8;
            double mean_p = (sp + eps * cp) / fmax(cp, 1.0);
            double mean_t = (st + eps * ct) / fmax(ct, 1.0);
            double comp_p = cp / mean_p;
            double comp_t = ct / mean_t;
            float loss = (float)fabs(comp_p - comp_t);  // skeleton_loss == 0 exactly
            for (int i = 0; i < out_size; ++i) out[i] = loss;
            g_acc[0] = 0.0; g_acc[1] = 0.0; g_acc[2] = 0.0; g_acc[3] = 0.0;
            __threadfence();
            g_ticket = 0u;
        }
    }
}

extern "C" void kernel_launch(void* const* d_in, const int* in_sizes, int n_in,
                              void* d_out, int out_size) {
    const float* pred   = (const float*)d_in[0];
    const float* target = (const float*)d_in[1];

    dim3 grid(DIMV / TX, DIMV / TY, 16);   // 6 x 8 x 16 = 768 blocks
    fused_skel_kernel<<<grid, NTHR>>>(pred, target, (float*)d_out, out_size);
}

// round 17
// speedup vs baseline: 1.6674x; 1.6674x over previous
#include <cuda_runtime.h>
#include <math.h>

// SoftSkeletonLoss reduces analytically:
//  - soft_skeletonize(sigmoid-range input) == 0 after iteration 1 (conv3x3x3 of a
//    strictly positive field is > 0 -> eroded = opened = 1 -> skeleton = clip(x-1,0,1)=0),
//    so skeleton_loss = 1 - EPS/EPS = 0 exactly.
//  - Remaining: connectivity_loss = |comp_p - comp_t| where
//      comp = cnt / mean_nb,  mean_nb = (sum_masked(conv3x3x3(field)) + EPS*cnt) / max(cnt,1)
//    pred:   field = (pred > 0) binarized (sigmoid(x)>0.5 <=> x>0), mask = pred>0
//    target: field = target raw,                                     mask = target>0
//
// Fused 27-point box-sum reduction (R10 skeleton): 256 threads, 4 CTAs/SM, tile
// 32x24x64, two z-planes per barrier with MLP=2 pure-issue prefetch, x-halo via
// warp shuffles at consume time, separable x-presums in smem, psum middle row
// from own registers. NEW: mask-weight DUAL accumulate —
//   sum = SUM_z' P(z') * (m(z'-1)+m(z')+m(z'+1)),  m==0 outside chunk —
// each psum is consumed immediately (no carried P float4s), branch-free FFMA.

#define DIMV   192
#define PLANE  (DIMV * DIMV)
#define TX     32
#define TY     24
#define CHUNK  64
#define HR     26              // halo rows (TY + 2)
#define SP     (HR * 32)       // one xs plane
#define NTHR   256
#define NBLK   (6 * 8 * 12)    // 576 blocks

// cnt_p, sum_p, cnt_t, sum_t (zero at module load; reset by last block each replay)
__device__ double   g_acc[4];
__device__ unsigned g_ticket;

__global__ __launch_bounds__(NTHR, 4)
void fused_skel_kernel(const float* __restrict__ pred,
                       const float* __restrict__ target,
                       float* __restrict__ out, int out_size) {
    __shared__ float sxs[2][2][SP];   // [buf][plane][row*32+col]
    __shared__ float red[8][2];

    const int tid = threadIdx.x;
    const int bx0 = blockIdx.x * TX;
    const int by0 = blockIdx.y * TY;

    const int  zc     = blockIdx.z;            // 0..11
    const bool isPred = (zc < 6);
    const int  s      = isPred ? zc : zc - 6;  // 0..5
    const int  n      = s / 3;                 // sample 0..1
    const int  z0     = (s % 3) * CHUNK;

    const float* __restrict__ src =
        (isPred ? pred : target) + (size_t)n * ((size_t)DIMV * PLANE);

    // ---- loader identity: tid<208 loads halo row ly = tid>>3, chunk jj ----
    const int  ly    = tid >> 3;               // 0..31 (rows 0..25 active)
    const int  jj    = tid & 7;
    const bool lact  = (tid < 8 * HR);         // 208 loader threads
    const int  gy    = by0 + ly - 1;
    const bool rowIn = lact && ((unsigned)gy < (unsigned)DIMV);
    const bool ldE   = ((jj == 0) && (bx0 > 0)) || ((jj == 7) && (bx0 + TX < DIMV));
    const int  eOff  = (jj == 0) ? -1 : 4;
    const int  xsOff = ly * 32 + 4 * jj;

    int zf = z0 - 1;   // first plane of next fetch pair
    const float* lp = src + (long long)zf * PLANE + gy * DIMV + (bx0 + 4 * jj);

    float4 v0, v1;     // raw chunks of the two most recently fetched planes
    float  e0, e1;     // boundary edge scalars

    // PURE-ISSUE fetch of planes zf, zf+1 (nothing consumes results here)
    auto fetch2 = [&]() {
        const bool a0 = rowIn && ((unsigned)zf       < (unsigned)DIMV);
        const bool a1 = rowIn && ((unsigned)(zf + 1) < (unsigned)DIMV);
        v0 = make_float4(0.f, 0.f, 0.f, 0.f); e0 = 0.f;
        v1 = make_float4(0.f, 0.f, 0.f, 0.f); e1 = 0.f;
        if (a0) { v0 = *(const float4*)lp; if (ldE) e0 = lp[eOff]; }
        if (a1) { const float* q = lp + PLANE;
                  v1 = *(const float4*)q; if (ldE) e1 = q[eOff]; }
        lp += 2 * PLANE; zf += 2;
    };

    // consume-time: x-halo shuffles + binarize (pred) + store 3-wide x-sums.
    // RETURNS the xs (kept in registers: it is the psum middle row).
    auto store_xs = [&](const float4& v, float e, float* dst) -> float4 {
        float up = __shfl_up_sync(0xffffffffu, v.w, 1);   // col gx0-1
        float dn = __shfl_down_sync(0xffffffffu, v.x, 1); // col gx0+4
        float el = (jj == 0) ? e : up;
        float er = (jj == 7) ? e : dn;
        float a0, a1, a2, a3, b0, b1;
        if (isPred) {
            a0 = v.x > 0.f ? 1.f : 0.f; a1 = v.y > 0.f ? 1.f : 0.f;
            a2 = v.z > 0.f ? 1.f : 0.f; a3 = v.w > 0.f ? 1.f : 0.f;
            b0 = el  > 0.f ? 1.f : 0.f; b1 = er  > 0.f ? 1.f : 0.f;
        } else { a0 = v.x; a1 = v.y; a2 = v.z; a3 = v.w; b0 = el; b1 = er; }
        float t01 = a0 + a1, t12 = a1 + a2, t23 = a2 + a3;
        float4 xs = make_float4(b0 + t01, t01 + a2, t12 + a3, t23 + b1);
        if (lact) *(float4*)(dst + xsOff) = xs;
        return xs;
    };

    // ---- compute identity: tid in [8, 200) -> voxel row ty = ly-1 (0..23) ----
    const bool  cact = (tid >= 8) && (tid < 8 + 8 * TY);
    const float cf   = cact ? 1.f : 0.f;
    // psum rows are xsOff-32 / xsOff+32; clamp for non-compute threads so the
    // LDS is always in-bounds (their contributions are nulled via mask = 0).
    const int   po   = cact ? xsOff : 64;

    // float 0/1 center mask scaled by `on` (activity / chunk-boundary zeroing)
    auto maskf = [&](const float4& c, float on) -> float4 {
        return make_float4(c.x > 0.f ? on : 0.f, c.y > 0.f ? on : 0.f,
                           c.z > 0.f ? on : 0.f, c.w > 0.f ? on : 0.f);
    };

    // psum: up/down rows from smem, middle row from the thread's own xs regs
    auto psum = [&](const float* sp, const float4& mid) -> float4 {
        float4 a = *(const float4*)(sp + po - 32);
        float4 c = *(const float4*)(sp + po + 32);
        return make_float4(a.x + mid.x + c.x, a.y + mid.y + c.y,
                           a.z + mid.z + c.z, a.w + mid.w + c.w);
    };

    float s0 = 0.f, s1 = 0.f, c0 = 0.f, c1 = 0.f;

    // ---- prologue: planes z0-1, z0 -> buf0; prefetch z0+1, z0+2 ----
    fetch2();
    float4 xsA = store_xs(v0, e0, sxs[0][0]);
    float4 xsB = store_xs(v1, e1, sxs[0][1]);
    float4 mfz = maskf(v1, cf);              // m(z0)
    fetch2();
    __syncthreads();
    {   // P(z0-1) weight = m(z0); P(z0) weight = m(z0) + m(z0+1)
        float4 pA = psum(sxs[0][0], xsA);
        float4 pB = psum(sxs[0][1], xsB);
        float4 mf1 = maskf(v0, cf);          // m(z0+1) (v0 = raw plane z0+1)
        s0 = fmaf(mfz.x, pA.x, s0); s1 = fmaf(mfz.y, pA.y, s1);
        s0 = fmaf(mfz.z, pA.z, s0); s1 = fmaf(mfz.w, pA.w, s1);
        float4 wB = make_float4(mfz.x + mf1.x, mfz.y + mf1.y,
                                mfz.z + mf1.z, mfz.w + mf1.w);
        s0 = fmaf(wB.x, pB.x, s0); s1 = fmaf(wB.y, pB.y, s1);
        s0 = fmaf(wB.z, pB.z, s0); s1 = fmaf(wB.w, pB.w, s1);
        c0 += mfz.x + mfz.y; c1 += mfz.z + mfz.w;   // cnt contribution of plane z0
    }

    // ---- main sweep: iteration k consumes P(z+1), P(z+2), z = z0+2k ----
    #pragma unroll 2
    for (int k = 0; k < CHUNK / 2; ++k) {
        const int  b    = (k + 1) & 1;            // destination buffer
        const bool last = (k == CHUNK / 2 - 1);
        const float on  = last ? 0.f : cf;        // plane z+2 == zE at k=31 -> mask 0
        float4 mB = maskf(v0, cf);                // m(z+1)
        float4 mC = maskf(v1, on);                // m(z+2)
        float4 xs0 = store_xs(v0, e0, sxs[b][0]); // xs of plane z+1
        float4 xs1 = store_xs(v1, e1, sxs[b][1]); // xs of plane z+2
        if (!last) fetch2();                      // prefetch planes z+3, z+4
        float4 t = make_float4(mB.x + mC.x, mB.y + mC.y, mB.z + mC.z, mB.w + mC.w);
        c0 += t.x + t.y;  c1 += t.z + t.w;        // cnt of planes z+1, z+2
        float4 w1 = make_float4(mfz.x + t.x, mfz.y + t.y, mfz.z + t.z, mfz.w + t.w);
        __syncthreads();
        float4 pC = psum(sxs[b][0], xs0);         // P(z+1)
        float4 pD = psum(sxs[b][1], xs1);         // P(z+2)
        float4 mD = maskf(v0, on);                // m(z+3) (v0 = raw z+3; 0 at k=31)
        float4 w2 = make_float4(t.x + mD.x, t.y + mD.y, t.z + mD.z, t.w + mD.w);

        s0 = fmaf(w1.x, pC.x, s0); s1 = fmaf(w1.y, pC.y, s1);
        s0 = fmaf(w1.z, pC.z, s0); s1 = fmaf(w1.w, pC.w, s1);
        s0 = fmaf(w2.x, pD.x, s0); s1 = fmaf(w2.y, pD.y, s1);
        s0 = fmaf(w2.z, pD.z, s0); s1 = fmaf(w2.w, pD.w, s1);

        mfz = mC;                                 // m(z+2) -> next iter's m(z)
    }

    float cnt = c0 + c1;
    float sum = s0 + s1;

    // ---- block reduction (8 warps) ----
    #pragma unroll
    for (int o = 16; o; o >>= 1) {
        cnt += __shfl_down_sync(0xffffffffu, cnt, o);
        sum += __shfl_down_sync(0xffffffffu, sum, o);
    }
    const int wid  = tid >> 5;
    const int lane = tid & 31;
    if (lane == 0) { red[wid][0] = cnt; red[wid][1] = sum; }
    __syncthreads();

    if (tid == 0) {
        float c2 = 0.f, s2 = 0.f;
        #pragma unroll
        for (int w = 0; w < 8; ++w) { c2 += red[w][0]; s2 += red[w][1]; }
        const int ai = isPred ? 0 : 2;
        atomicAdd(&g_acc[ai],     (double)c2);
        atomicAdd(&g_acc[ai + 1], (double)s2);
        __threadfence();
        unsigned t = atomicAdd(&g_ticket, 1u);
        if (t == NBLK - 1) {
            // last block: finalize, write output, reset for next graph replay
            __threadfence();
            double cp = atomicAdd(&g_acc[0], 0.0);
            double sp = atomicAdd(&g_acc[1], 0.0);
            double ct = atomicAdd(&g_acc[2], 0.0);
            double st = atomicAdd(&g_acc[3], 0.0);
            const double eps = 1e-8;
            double mean_p = (sp + eps * cp) / fmax(cp, 1.0);
            double mean_t = (st + eps * ct) / fmax(ct, 1.0);
            double comp_p = cp / mean_p;
            double comp_t = ct / mean_t;
            float loss = (float)fabs(comp_p - comp_t);  // skeleton_loss == 0 exactly
            for (int i = 0; i < out_size; ++i) out[i] = loss;
            g_acc[0] = 0.0; g_acc[1] = 0.0; g_acc[2] = 0.0; g_acc[3] = 0.0;
            __threadfence();
            g_ticket = 0u;
        }
    }
}

extern "C" void kernel_launch(void* const* d_in, const int* in_sizes, int n_in,
                              void* d_out, int out_size) {
    const float* pred   = (const float*)d_in[0];
    const float* target = (const float*)d_in[1];

    dim3 grid(DIMV / TX, DIMV / TY, 12);   // 6 x 8 x 12 = 576 blocks
    fused_skel_kernel<<<grid, NTHR>>>(pred, target, (float*)d_out, out_size);
}